// round 12
// baseline (speedup 1.0000x reference)
#include <cuda_runtime.h>
#include <cuda_bf16.h>
#include <cstdint>

#define N_ 128
#define D_ 2048
#define C_ 256
#define K_ 8192
#define NJ 3          // Taylor terms j=1..3 (j=0 handled as +256 constant)

#define LOG2E 1.4426950408889634f
#define LN2   0.6931471805599453f
#define INV_T (1.0f / 0.07f)

__device__ float g_penult[N_ * C_];           // zero-init; head re-zeroes after use
__device__ __nv_bfloat16 g_A[NJ * N_ * C_];   // A_j[n][c] = dist^j / j!

__device__ __forceinline__ float ex2f_(float x) {
    float y; asm("ex2.approx.f32 %0, %1;" : "=f"(y) : "f"(x)); return y;
}
__device__ __forceinline__ float lg2f_(float x) {
    float y; asm("lg2.approx.f32 %0, %1;" : "=f"(y) : "f"(x)); return y;
}
__device__ __forceinline__ uint32_t su32(const void* p) {
    return (uint32_t)__cvta_generic_to_shared(p);
}

// ---------------------------------------------------------------------------
// prep: A powers (bf16), labels = 0
// ---------------------------------------------------------------------------
__global__ void prep_kernel(const float* __restrict__ dist,
                            float* __restrict__ out) {
    int n = blockIdx.x, c = threadIdx.x;
    float d = dist[n * C_ + c];
    float p = d;
    g_A[(0 * N_ + n) * C_ + c] = __float2bfloat16(p);
    p *= d;
    g_A[(1 * N_ + n) * C_ + c] = __float2bfloat16(p * 0.5f);
    p *= d;
    g_A[(2 * N_ + n) * C_ + c] = __float2bfloat16(p * (1.0f / 6.0f));
    if (c == 0) out[N_ * (K_ + 1) + n] = 0.0f;   // labels
}

// ---------------------------------------------------------------------------
// gemm1: g_penult += img @ W_f  (fp32 split-K x32, 128 CTAs; 1M atomics)
// ---------------------------------------------------------------------------
__global__ void gemm1_kernel(const float* __restrict__ img,
                             const float* __restrict__ Wf) {
    __shared__ float s_img[128][64];   // 32 KB
    int tid = threadIdx.x;
    int c = blockIdx.x * 64 + (tid & 63);
    int rblk = tid >> 6;
    int d0 = blockIdx.y * 64;

    for (int i = tid; i < 128 * 64; i += 256) {
        int r = i >> 6, dd = i & 63;
        s_img[r][dd] = img[r * D_ + d0 + dd];
    }
    __syncthreads();

    float acc[32];
#pragma unroll
    for (int r = 0; r < 32; r++) acc[r] = 0.0f;

    for (int ds = 0; ds < 64; ds += 4) {
        float w0 = Wf[(d0 + ds + 0) * C_ + c];
        float w1 = Wf[(d0 + ds + 1) * C_ + c];
        float w2 = Wf[(d0 + ds + 2) * C_ + c];
        float w3 = Wf[(d0 + ds + 3) * C_ + c];
#pragma unroll
        for (int r = 0; r < 32; r++) {
            float4 v = *reinterpret_cast<const float4*>(&s_img[rblk * 32 + r][ds]);
            acc[r] = fmaf(v.x, w0, acc[r]);
            acc[r] = fmaf(v.y, w1, acc[r]);
            acc[r] = fmaf(v.z, w2, acc[r]);
            acc[r] = fmaf(v.w, w3, acc[r]);
        }
    }
#pragma unroll
    for (int r = 0; r < 32; r++)
        atomicAdd(&g_penult[(rblk * 32 + r) * C_ + c], acc[r]);
}

// ---------------------------------------------------------------------------
// head: split-K x4, block 1024; concurrent with lneg (disjoint outputs).
// ---------------------------------------------------------------------------
__global__ __launch_bounds__(1024, 1)
void head_kernel(const float* __restrict__ Wc,
                 const float* __restrict__ bc,
                 const float* __restrict__ bf,
                 const float* __restrict__ dist,
                 float* __restrict__ out) {
    __shared__ float sp[C_];
    __shared__ float part[3][C_];
    __shared__ float sred[8];
    int n = blockIdx.x;
    int tid = threadIdx.x;
    int ks = tid >> 8;        // 0..3 (64 d's each)
    int c = tid & 255;

    if (ks == 0) sp[c] = g_penult[n * C_ + c] + bf[c];
    __syncthreads();
    if (ks == 0) g_penult[n * C_ + c] = 0.0f;   // reset accumulator for replay

    float acc = 0.0f;
    int d0 = ks * 64;
#pragma unroll 16
    for (int d = 0; d < 64; d++)
        acc = fmaf(sp[d0 + d], Wc[(d0 + d) * C_ + c], acc);

    if (ks) part[ks - 1][c] = acc;
    __syncthreads();
    if (ks != 0) return;

    acc += bc[c] + part[0][c] + part[1][c] + part[2][c];

    out[N_ * (K_ + 1) + N_ + n * C_ + c] = acc;   // f_logit

    float v = acc * acc;
#pragma unroll
    for (int o = 16; o; o >>= 1) v += __shfl_xor_sync(0xffffffffu, v, o);
    if ((c & 31) == 0) sred[c >> 5] = v;
    __syncthreads();
    float ss = sred[0] + sred[1] + sred[2] + sred[3] +
               sred[4] + sred[5] + sred[6] + sred[7];
    __syncthreads();

    float inv = 1.0f / fmaxf(sqrtf(ss), 1e-12f);
    float t = dist[n * C_ + c] * acc * inv;
    float e = ex2f_(t * LOG2E);
#pragma unroll
    for (int o = 16; o; o >>= 1) e += __shfl_xor_sync(0xffffffffu, e, o);
    if ((c & 31) == 0) sred[c >> 5] = e;
    __syncthreads();
    if (c == 0) {
        float s = sred[0] + sred[1] + sred[2] + sred[3] +
                  sred[4] + sred[5] + sred[6] + sred[7];
        out[n * (K_ + 1)] = lg2f_(s) * (LN2 * INV_T);
    }
}

// ---------------------------------------------------------------------------
// lneg v5: grid 256 (32-wide k tiles), block 256, 2 CTAs/SM, smem 80KB.
// Ping-pong register fragments in a fully-unrolled kt loop (no copies).
// ---------------------------------------------------------------------------
#define SMA   0
#define SMB   65536
#define SMTOT 81920

__device__ __forceinline__ void ld_a_x4(uint32_t addr, uint32_t* a) {
    asm volatile("ldmatrix.sync.aligned.m8n8.x4.shared.b16 {%0,%1,%2,%3}, [%4];"
                 : "=r"(a[0]), "=r"(a[1]), "=r"(a[2]), "=r"(a[3]) : "r"(addr));
}

__global__ __launch_bounds__(256, 2)
void lneg_kernel(const float* __restrict__ q,
                 float* __restrict__ out) {
    extern __shared__ char smem[];
    uint32_t sb = su32(smem);
    int tid = threadIdx.x;
    int kx = tid & 31, cg = tid >> 5;
    int k0 = blockIdx.x * 32;

    // ---- q column-slice -> regs; sum of squares ----
    float qv[32];
    float ss = 0.0f;
    {
        const float* qp = q + (size_t)(cg * 32) * K_ + k0 + kx;
#pragma unroll
        for (int i = 0; i < 32; i++) {
            qv[i] = qp[(size_t)i * K_];
            ss = fmaf(qv[i], qv[i], ss);
        }
    }
    float* ssp = (float*)(smem + SMA);          // alias into A region (pre-loop)
    float* invp = (float*)(smem + SMA + 1024);
    ssp[cg * 32 + kx] = ss;
    __syncthreads();
    if (tid < 32) {
        float s = 0.0f;
#pragma unroll
        for (int g = 0; g < 8; g++) s += ssp[g * 32 + tid];
        invp[tid] = 1.0f / fmaxf(sqrtf(s), 1e-12f);
    }
    __syncthreads();

    // ---- b = q*inv and running power p, packed bf16x2 in regs ----
    __nv_bfloat162 b2[16], p2[16];
    {
        float iv = invp[kx];
#pragma unroll
        for (int i = 0; i < 16; ++i) {
            b2[i] = __floats2bfloat162_rn(qv[2 * i] * iv, qv[2 * i + 1] * iv);
            p2[i] = b2[i];
        }
    }

    int warp = tid >> 5, lane = tid & 31;
    int mrow = (warp >> 1) * 32;
    int ncol = (warp & 1) * 16;

    float acc[2][2][4];
#pragma unroll
    for (int mt = 0; mt < 2; mt++)
#pragma unroll
        for (int nt = 0; nt < 2; nt++)
#pragma unroll
            for (int i = 0; i < 4; i++) acc[mt][nt][i] = 0.0f;

    int a_row0 = mrow + (lane & 15);
    int a_chL  = lane >> 4;
    int t4 = lane >> 3;
    int b_row = ncol + ((t4 >> 1) << 3) + (lane & 7);
    int b_chL = t4 & 1;

    uint32_t Ab = sb + SMA;
    uint32_t Bb = sb + SMB;

    // precomputed base addresses for fragment loads
    uint32_t aAddr0 = Ab + (a_row0) * 512;
    uint32_t aAddr1 = Ab + (a_row0 + 16) * 512;
    uint32_t bAddr  = Bb + b_row * 512;
    int aSw0 = (a_row0) & 7, aSw1 = (a_row0 + 16) & 7, bSw = b_row & 7;

    for (int j = 0; j < NJ; ++j) {
        __syncthreads();   // inv consumed (j=0) / prior A+B consumption done
        // stage A_j [128 x 256] -> swizzled tile
        const uint4* Asrc = (const uint4*)(g_A + (size_t)j * N_ * C_);
#pragma unroll
        for (int t = 0; t < 16; ++t) {
            int lin = t * 256 + tid;
            int m = lin >> 5;
            int ch = lin & 31;
            *(uint4*)(smem + SMA + m * 512 + ((ch ^ (m & 7)) << 4)) = Asrc[lin];
        }
        // build B_j = b^(j+1) into the single B slot from registers
#pragma unroll
        for (int i = 0; i < 16; ++i) {
            int c2 = cg * 32 + i * 2;
            uint32_t off = (uint32_t)(kx * 512 + (((c2 >> 3) ^ (kx & 7)) << 4)
                                      + (c2 & 7) * 2);
            *(uint32_t*)(smem + SMB + off) = *(uint32_t*)&p2[i];
            p2[i] = __hmul2(p2[i], b2[i]);
        }
        __syncthreads();

        // ping-pong fragment buffers; fully unrolled -> no register copies
        uint32_t a_f[2][2][4], b_f[2][4];
        ld_a_x4(aAddr0 + ((a_chL ^ aSw0) << 4), a_f[0][0]);
        ld_a_x4(aAddr1 + ((a_chL ^ aSw1) << 4), a_f[0][1]);
        ld_a_x4(bAddr + ((b_chL ^ bSw) << 4), b_f[0]);

#pragma unroll
        for (int kt = 0; kt < 16; ++kt) {
            int cur = kt & 1, nxt = cur ^ 1;
            if (kt < 15) {
                int ch = (kt + 1) * 2;
                ld_a_x4(aAddr0 + (((ch + a_chL) ^ aSw0) << 4), a_f[nxt][0]);
                ld_a_x4(aAddr1 + (((ch + a_chL) ^ aSw1) << 4), a_f[nxt][1]);
                ld_a_x4(bAddr + (((ch + b_chL) ^ bSw) << 4), b_f[nxt]);
            }
#pragma unroll
            for (int mt = 0; mt < 2; ++mt)
#pragma unroll
                for (int nt = 0; nt < 2; ++nt)
                    asm volatile(
                        "mma.sync.aligned.m16n8k16.row.col.f32.bf16.bf16.f32 "
                        "{%0,%1,%2,%3}, {%4,%5,%6,%7}, {%8,%9}, {%0,%1,%2,%3};"
                        : "+f"(acc[mt][nt][0]), "+f"(acc[mt][nt][1]),
                          "+f"(acc[mt][nt][2]), "+f"(acc[mt][nt][3])
                        : "r"(a_f[cur][mt][0]), "r"(a_f[cur][mt][1]),
                          "r"(a_f[cur][mt][2]), "r"(a_f[cur][mt][3]),
                          "r"(b_f[cur][nt * 2]), "r"(b_f[cur][nt * 2 + 1]));
        }
    }

    const float sc = LN2 * INV_T;
#pragma unroll
    for (int mt = 0; mt < 2; ++mt) {
#pragma unroll
        for (int nt = 0; nt < 2; ++nt) {
            int r = mrow + mt * 16 + (lane >> 2);
            int col = k0 + ncol + nt * 8 + (lane & 3) * 2;
            int base = r * (K_ + 1) + 1 + col;
            out[base]     = lg2f_(256.0f + acc[mt][nt][0]) * sc;
            out[base + 1] = lg2f_(256.0f + acc[mt][nt][1]) * sc;
            int base2 = (r + 8) * (K_ + 1) + 1 + col;
            out[base2]     = lg2f_(256.0f + acc[mt][nt][2]) * sc;
            out[base2 + 1] = lg2f_(256.0f + acc[mt][nt][3]) * sc;
        }
    }
}

extern "C" void kernel_launch(void* const* d_in, const int* in_sizes, int n_in,
                              void* d_out, int out_size) {
    const float* img  = (const float*)d_in[0];
    const float* Wf   = (const float*)d_in[1];
    const float* bf   = (const float*)d_in[2];
    const float* Wc   = (const float*)d_in[3];
    const float* bc   = (const float*)d_in[4];
    const float* dist = (const float*)d_in[5];
    const float* q    = (const float*)d_in[6];
    float* out = (float*)d_out;

    static cudaStream_t s1 = nullptr;
    static cudaEvent_t ev0 = nullptr, ev1 = nullptr;
    if (s1 == nullptr) {
        cudaStreamCreateWithFlags(&s1, cudaStreamNonBlocking);
        cudaEventCreateWithFlags(&ev0, cudaEventDisableTiming);
        cudaEventCreateWithFlags(&ev1, cudaEventDisableTiming);
        cudaFuncSetAttribute(lneg_kernel,
                             cudaFuncAttributeMaxDynamicSharedMemorySize, SMTOT);
    }

    // main: prep -> lneg          (l_neg columns)
    // s1:   gemm1 -> head         (f_logit, l_pos)
    cudaEventRecord(ev0, 0);
    cudaStreamWaitEvent(s1, ev0, 0);
    gemm1_kernel<<<dim3(4, 32), 256, 0, s1>>>(img, Wf);
    head_kernel<<<N_, 1024, 0, s1>>>(Wc, bc, bf, dist, out);
    cudaEventRecord(ev1, s1);
    prep_kernel<<<N_, C_>>>(dist, out);
    lneg_kernel<<<K_ / 32, 256, SMTOT>>>(q, out);
    cudaStreamWaitEvent(0, ev1, 0);
}

// round 13
// speedup vs baseline: 1.1483x; 1.1483x over previous
#include <cuda_runtime.h>
#include <cuda_bf16.h>
#include <cstdint>

#define N_ 128
#define D_ 2048
#define C_ 256
#define K_ 8192
#define NJ 2          // Taylor terms j=1..2 (j=0 handled as +256 constant)

#define LOG2E 1.4426950408889634f
#define LN2   0.6931471805599453f
#define INV_T (1.0f / 0.07f)

__device__ float g_penult[N_ * C_];           // zero-init; head re-zeroes after use
__device__ __nv_bfloat16 g_A[NJ * N_ * C_];   // A_j[n][c] = dist^j / j!

__device__ __forceinline__ float ex2f_(float x) {
    float y; asm("ex2.approx.f32 %0, %1;" : "=f"(y) : "f"(x)); return y;
}
__device__ __forceinline__ float lg2f_(float x) {
    float y; asm("lg2.approx.f32 %0, %1;" : "=f"(y) : "f"(x)); return y;
}
__device__ __forceinline__ uint32_t su32(const void* p) {
    return (uint32_t)__cvta_generic_to_shared(p);
}

// ---------------------------------------------------------------------------
// prep: A powers (bf16), labels = 0
// ---------------------------------------------------------------------------
__global__ void prep_kernel(const float* __restrict__ dist,
                            float* __restrict__ out) {
    int n = blockIdx.x, c = threadIdx.x;
    float d = dist[n * C_ + c];
    g_A[(0 * N_ + n) * C_ + c] = __float2bfloat16(d);
    g_A[(1 * N_ + n) * C_ + c] = __float2bfloat16(d * d * 0.5f);
    if (c == 0) out[N_ * (K_ + 1) + n] = 0.0f;   // labels
}

// ---------------------------------------------------------------------------
// gemm1: g_penult += img @ W_f  (fp32 split-K x64, 256 CTAs) — R11 config
// ---------------------------------------------------------------------------
__global__ void gemm1_kernel(const float* __restrict__ img,
                             const float* __restrict__ Wf) {
    __shared__ float s_img[128][32];   // 16 KB
    int tid = threadIdx.x;
    int c = blockIdx.x * 64 + (tid & 63);
    int rblk = tid >> 6;
    int d0 = blockIdx.y * 32;

    for (int i = tid; i < 128 * 32; i += 256) {
        int r = i >> 5, dd = i & 31;
        s_img[r][dd] = img[r * D_ + d0 + dd];
    }
    __syncthreads();

    float acc[32];
#pragma unroll
    for (int r = 0; r < 32; r++) acc[r] = 0.0f;

    for (int ds = 0; ds < 32; ds += 4) {
        float w0 = Wf[(d0 + ds + 0) * C_ + c];
        float w1 = Wf[(d0 + ds + 1) * C_ + c];
        float w2 = Wf[(d0 + ds + 2) * C_ + c];
        float w3 = Wf[(d0 + ds + 3) * C_ + c];
#pragma unroll
        for (int r = 0; r < 32; r++) {
            float4 v = *reinterpret_cast<const float4*>(&s_img[rblk * 32 + r][ds]);
            acc[r] = fmaf(v.x, w0, acc[r]);
            acc[r] = fmaf(v.y, w1, acc[r]);
            acc[r] = fmaf(v.z, w2, acc[r]);
            acc[r] = fmaf(v.w, w3, acc[r]);
        }
    }
#pragma unroll
    for (int r = 0; r < 32; r++)
        atomicAdd(&g_penult[(rblk * 32 + r) * C_ + c], acc[r]);
}

// ---------------------------------------------------------------------------
// head: 2 rows per CTA (grid 64), split-K x4 within each row.
//       Halves Wc L2 traffic; concurrent with lneg (disjoint outputs).
// ---------------------------------------------------------------------------
__global__ __launch_bounds__(1024, 1)
void head_kernel(const float* __restrict__ Wc,
                 const float* __restrict__ bc,
                 const float* __restrict__ bf,
                 const float* __restrict__ dist,
                 float* __restrict__ out) {
    __shared__ float sp[2][C_];
    __shared__ float part[3][2][C_];
    __shared__ float sred[2][8];
    int n0 = blockIdx.x * 2;
    int tid = threadIdx.x;
    int ks = tid >> 8;        // 0..3 (64 d's each)
    int c = tid & 255;

    if (ks < 2) sp[ks][c] = g_penult[(n0 + ks) * C_ + c] + bf[c];
    __syncthreads();
    if (ks < 2) g_penult[(n0 + ks) * C_ + c] = 0.0f;   // reset for replay

    float a0 = 0.0f, a1 = 0.0f;
    int d0 = ks * 64;
#pragma unroll 16
    for (int d = 0; d < 64; d++) {
        float w = Wc[(d0 + d) * C_ + c];
        a0 = fmaf(sp[0][d0 + d], w, a0);
        a1 = fmaf(sp[1][d0 + d], w, a1);
    }

    if (ks) { part[ks - 1][0][c] = a0; part[ks - 1][1][c] = a1; }
    __syncthreads();
    if (ks != 0) return;

    float b = bc[c];
    a0 += b + part[0][0][c] + part[1][0][c] + part[2][0][c];
    a1 += b + part[0][1][c] + part[1][1][c] + part[2][1][c];

    out[N_ * (K_ + 1) + N_ + (n0 + 0) * C_ + c] = a0;   // f_logit row n0
    out[N_ * (K_ + 1) + N_ + (n0 + 1) * C_ + c] = a1;   // f_logit row n0+1

    float v0 = a0 * a0, v1 = a1 * a1;
#pragma unroll
    for (int o = 16; o; o >>= 1) {
        v0 += __shfl_xor_sync(0xffffffffu, v0, o);
        v1 += __shfl_xor_sync(0xffffffffu, v1, o);
    }
    if ((c & 31) == 0) { sred[0][c >> 5] = v0; sred[1][c >> 5] = v1; }
    __syncthreads();
    float ss0 = 0.0f, ss1 = 0.0f;
#pragma unroll
    for (int g = 0; g < 8; g++) { ss0 += sred[0][g]; ss1 += sred[1][g]; }
    __syncthreads();

    float inv0 = 1.0f / fmaxf(sqrtf(ss0), 1e-12f);
    float inv1 = 1.0f / fmaxf(sqrtf(ss1), 1e-12f);
    float e0 = ex2f_(dist[(n0 + 0) * C_ + c] * a0 * inv0 * LOG2E);
    float e1 = ex2f_(dist[(n0 + 1) * C_ + c] * a1 * inv1 * LOG2E);
#pragma unroll
    for (int o = 16; o; o >>= 1) {
        e0 += __shfl_xor_sync(0xffffffffu, e0, o);
        e1 += __shfl_xor_sync(0xffffffffu, e1, o);
    }
    if ((c & 31) == 0) { sred[0][c >> 5] = e0; sred[1][c >> 5] = e1; }
    __syncthreads();
    if (c == 0) {
        float s0 = 0.0f, s1 = 0.0f;
#pragma unroll
        for (int g = 0; g < 8; g++) { s0 += sred[0][g]; s1 += sred[1][g]; }
        out[(n0 + 0) * (K_ + 1)] = lg2f_(s0) * (LN2 * INV_T);
        out[(n0 + 1) * (K_ + 1)] = lg2f_(s1) * (LN2 * INV_T);
    }
}

// ---------------------------------------------------------------------------
// lneg v6: J=2. grid 256 (32-wide k tiles), block 256, 2 CTAs/SM, smem 80KB.
// ---------------------------------------------------------------------------
#define SMA   0
#define SMB   65536
#define SMTOT 81920

__device__ __forceinline__ void ld_a_x4(uint32_t addr, uint32_t* a) {
    asm volatile("ldmatrix.sync.aligned.m8n8.x4.shared.b16 {%0,%1,%2,%3}, [%4];"
                 : "=r"(a[0]), "=r"(a[1]), "=r"(a[2]), "=r"(a[3]) : "r"(addr));
}

__global__ __launch_bounds__(256, 2)
void lneg_kernel(const float* __restrict__ q,
                 float* __restrict__ out) {
    extern __shared__ char smem[];
    uint32_t sb = su32(smem);
    int tid = threadIdx.x;
    int kx = tid & 31, cg = tid >> 5;
    int k0 = blockIdx.x * 32;

    // ---- q column-slice -> regs; sum of squares ----
    float qv[32];
    float ss = 0.0f;
    {
        const float* qp = q + (size_t)(cg * 32) * K_ + k0 + kx;
#pragma unroll
        for (int i = 0; i < 32; i++) {
            qv[i] = qp[(size_t)i * K_];
            ss = fmaf(qv[i], qv[i], ss);
        }
    }
    float* ssp = (float*)(smem + SMA);          // alias into A region (pre-loop)
    float* invp = (float*)(smem + SMA + 1024);
    ssp[cg * 32 + kx] = ss;
    __syncthreads();
    if (tid < 32) {
        float s = 0.0f;
#pragma unroll
        for (int g = 0; g < 8; g++) s += ssp[g * 32 + tid];
        invp[tid] = 1.0f / fmaxf(sqrtf(s), 1e-12f);
    }
    __syncthreads();

    // ---- b = q*inv and running power p, packed bf16x2 in regs ----
    __nv_bfloat162 b2[16], p2[16];
    {
        float iv = invp[kx];
#pragma unroll
        for (int i = 0; i < 16; ++i) {
            b2[i] = __floats2bfloat162_rn(qv[2 * i] * iv, qv[2 * i + 1] * iv);
            p2[i] = b2[i];
        }
    }

    int warp = tid >> 5, lane = tid & 31;
    int mrow = (warp >> 1) * 32;
    int ncol = (warp & 1) * 16;

    float acc[2][2][4];
#pragma unroll
    for (int mt = 0; mt < 2; mt++)
#pragma unroll
        for (int nt = 0; nt < 2; nt++)
#pragma unroll
            for (int i = 0; i < 4; i++) acc[mt][nt][i] = 0.0f;

    int a_row0 = mrow + (lane & 15);
    int a_chL  = lane >> 4;
    int t4 = lane >> 3;
    int b_row = ncol + ((t4 >> 1) << 3) + (lane & 7);
    int b_chL = t4 & 1;

    uint32_t aAddr0 = sb + SMA + (a_row0) * 512;
    uint32_t aAddr1 = sb + SMA + (a_row0 + 16) * 512;
    uint32_t bAddr  = sb + SMB + b_row * 512;
    int aSw0 = (a_row0) & 7, aSw1 = (a_row0 + 16) & 7, bSw = b_row & 7;

    for (int j = 0; j < NJ; ++j) {
        __syncthreads();   // inv consumed (j=0) / prior A+B consumption done
        // stage A_j [128 x 256] -> swizzled tile
        const uint4* Asrc = (const uint4*)(g_A + (size_t)j * N_ * C_);
#pragma unroll
        for (int t = 0; t < 16; ++t) {
            int lin = t * 256 + tid;
            int m = lin >> 5;
            int ch = lin & 31;
            *(uint4*)(smem + SMA + m * 512 + ((ch ^ (m & 7)) << 4)) = Asrc[lin];
        }
        // build B_j = b^(j+1) into the single B slot from registers
#pragma unroll
        for (int i = 0; i < 16; ++i) {
            int c2 = cg * 32 + i * 2;
            uint32_t off = (uint32_t)(kx * 512 + (((c2 >> 3) ^ (kx & 7)) << 4)
                                      + (c2 & 7) * 2);
            *(uint32_t*)(smem + SMB + off) = *(uint32_t*)&p2[i];
            p2[i] = __hmul2(p2[i], b2[i]);
        }
        __syncthreads();

        uint32_t a_f[2][2][4], b_f[2][4];
        ld_a_x4(aAddr0 + ((a_chL ^ aSw0) << 4), a_f[0][0]);
        ld_a_x4(aAddr1 + ((a_chL ^ aSw1) << 4), a_f[0][1]);
        ld_a_x4(bAddr + ((b_chL ^ bSw) << 4), b_f[0]);

#pragma unroll
        for (int kt = 0; kt < 16; ++kt) {
            int cur = kt & 1, nxt = cur ^ 1;
            if (kt < 15) {
                int ch = (kt + 1) * 2;
                ld_a_x4(aAddr0 + (((ch + a_chL) ^ aSw0) << 4), a_f[nxt][0]);
                ld_a_x4(aAddr1 + (((ch + a_chL) ^ aSw1) << 4), a_f[nxt][1]);
                ld_a_x4(bAddr + (((ch + b_chL) ^ bSw) << 4), b_f[nxt]);
            }
#pragma unroll
            for (int mt = 0; mt < 2; ++mt)
#pragma unroll
                for (int nt = 0; nt < 2; ++nt)
                    asm volatile(
                        "mma.sync.aligned.m16n8k16.row.col.f32.bf16.bf16.f32 "
                        "{%0,%1,%2,%3}, {%4,%5,%6,%7}, {%8,%9}, {%0,%1,%2,%3};"
                        : "+f"(acc[mt][nt][0]), "+f"(acc[mt][nt][1]),
                          "+f"(acc[mt][nt][2]), "+f"(acc[mt][nt][3])
                        : "r"(a_f[cur][mt][0]), "r"(a_f[cur][mt][1]),
                          "r"(a_f[cur][mt][2]), "r"(a_f[cur][mt][3]),
                          "r"(b_f[cur][nt * 2]), "r"(b_f[cur][nt * 2 + 1]));
        }
    }

    const float sc = LN2 * INV_T;
#pragma unroll
    for (int mt = 0; mt < 2; ++mt) {
#pragma unroll
        for (int nt = 0; nt < 2; ++nt) {
            int r = mrow + mt * 16 + (lane >> 2);
            int col = k0 + ncol + nt * 8 + (lane & 3) * 2;
            int base = r * (K_ + 1) + 1 + col;
            out[base]     = lg2f_(256.0f + acc[mt][nt][0]) * sc;
            out[base + 1] = lg2f_(256.0f + acc[mt][nt][1]) * sc;
            int base2 = (r + 8) * (K_ + 1) + 1 + col;
            out[base2]     = lg2f_(256.0f + acc[mt][nt][2]) * sc;
            out[base2 + 1] = lg2f_(256.0f + acc[mt][nt][3]) * sc;
        }
    }
}

extern "C" void kernel_launch(void* const* d_in, const int* in_sizes, int n_in,
                              void* d_out, int out_size) {
    const float* img  = (const float*)d_in[0];
    const float* Wf   = (const float*)d_in[1];
    const float* bf   = (const float*)d_in[2];
    const float* Wc   = (const float*)d_in[3];
    const float* bc   = (const float*)d_in[4];
    const float* dist = (const float*)d_in[5];
    const float* q    = (const float*)d_in[6];
    float* out = (float*)d_out;

    static cudaStream_t s1 = nullptr;
    static cudaEvent_t ev0 = nullptr, ev1 = nullptr;
    if (s1 == nullptr) {
        cudaStreamCreateWithFlags(&s1, cudaStreamNonBlocking);
        cudaEventCreateWithFlags(&ev0, cudaEventDisableTiming);
        cudaEventCreateWithFlags(&ev1, cudaEventDisableTiming);
        cudaFuncSetAttribute(lneg_kernel,
                             cudaFuncAttributeMaxDynamicSharedMemorySize, SMTOT);
    }

    // main: prep -> lneg          (l_neg columns)
    // s1:   gemm1 -> head         (f_logit, l_pos)
    cudaEventRecord(ev0, 0);
    cudaStreamWaitEvent(s1, ev0, 0);
    gemm1_kernel<<<dim3(4, 64), 256, 0, s1>>>(img, Wf);
    head_kernel<<<N_ / 2, 1024, 0, s1>>>(Wc, bc, bf, dist, out);
    cudaEventRecord(ev1, s1);
    prep_kernel<<<N_, C_>>>(dist, out);
    lneg_kernel<<<K_ / 32, 256, SMTOT>>>(q, out);
    cudaStreamWaitEvent(0, ev1, 0);
}

// round 14
// speedup vs baseline: 1.2434x; 1.0828x over previous
#include <cuda_runtime.h>
#include <cuda_bf16.h>
#include <cstdint>

#define N_ 128
#define D_ 2048
#define C_ 256
#define K_ 8192
#define NJ 2          // Taylor terms j=1..2 (j=0 handled as +256 constant)

#define LOG2E 1.4426950408889634f
#define LN2   0.6931471805599453f
#define INV_T (1.0f / 0.07f)

__device__ float g_penult[N_ * C_];           // zero-init; head re-zeroes after use
__device__ __nv_bfloat16 g_A[NJ * N_ * C_];   // A_j[n][c] = dist^j / j!

__device__ __forceinline__ float ex2f_(float x) {
    float y; asm("ex2.approx.f32 %0, %1;" : "=f"(y) : "f"(x)); return y;
}
__device__ __forceinline__ float lg2f_(float x) {
    float y; asm("lg2.approx.f32 %0, %1;" : "=f"(y) : "f"(x)); return y;
}
__device__ __forceinline__ uint32_t su32(const void* p) {
    return (uint32_t)__cvta_generic_to_shared(p);
}

// ---------------------------------------------------------------------------
// prep: A powers (bf16), labels = 0
// ---------------------------------------------------------------------------
__global__ void prep_kernel(const float* __restrict__ dist,
                            float* __restrict__ out) {
    int n = blockIdx.x, c = threadIdx.x;
    float d = dist[n * C_ + c];
    g_A[(0 * N_ + n) * C_ + c] = __float2bfloat16(d);
    g_A[(1 * N_ + n) * C_ + c] = __float2bfloat16(d * d * 0.5f);
    if (c == 0) out[N_ * (K_ + 1) + n] = 0.0f;   // labels
}

// ---------------------------------------------------------------------------
// gemm1: g_penult += img @ W_f  (fp32 split-K x64, 256 CTAs)
// ---------------------------------------------------------------------------
__global__ void gemm1_kernel(const float* __restrict__ img,
                             const float* __restrict__ Wf) {
    __shared__ float s_img[128][32];   // 16 KB
    int tid = threadIdx.x;
    int c = blockIdx.x * 64 + (tid & 63);
    int rblk = tid >> 6;
    int d0 = blockIdx.y * 32;

    for (int i = tid; i < 128 * 32; i += 256) {
        int r = i >> 5, dd = i & 31;
        s_img[r][dd] = img[r * D_ + d0 + dd];
    }
    __syncthreads();

    float acc[32];
#pragma unroll
    for (int r = 0; r < 32; r++) acc[r] = 0.0f;

    for (int ds = 0; ds < 32; ds += 4) {
        float w0 = Wf[(d0 + ds + 0) * C_ + c];
        float w1 = Wf[(d0 + ds + 1) * C_ + c];
        float w2 = Wf[(d0 + ds + 2) * C_ + c];
        float w3 = Wf[(d0 + ds + 3) * C_ + c];
#pragma unroll
        for (int r = 0; r < 32; r++) {
            float4 v = *reinterpret_cast<const float4*>(&s_img[rblk * 32 + r][ds]);
            acc[r] = fmaf(v.x, w0, acc[r]);
            acc[r] = fmaf(v.y, w1, acc[r]);
            acc[r] = fmaf(v.z, w2, acc[r]);
            acc[r] = fmaf(v.w, w3, acc[r]);
        }
    }
#pragma unroll
    for (int r = 0; r < 32; r++)
        atomicAdd(&g_penult[(rblk * 32 + r) * C_ + c], acc[r]);
}

// ---------------------------------------------------------------------------
// head: block 512 (2 rows/CTA, split-K x2) — small enough to co-reside with
//       two lneg CTAs (regs+threads+smem all fit).
// ---------------------------------------------------------------------------
__global__ __launch_bounds__(512, 1)
void head_kernel(const float* __restrict__ Wc,
                 const float* __restrict__ bc,
                 const float* __restrict__ bf,
                 const float* __restrict__ dist,
                 float* __restrict__ out) {
    __shared__ float sp[2][C_];
    __shared__ float part[2][C_];
    __shared__ float sred[2][8];
    int n0 = blockIdx.x * 2;
    int tid = threadIdx.x;
    int ks = tid >> 8;        // 0..1 (128 d's each)
    int c = tid & 255;

    sp[ks][c] = g_penult[(n0 + ks) * C_ + c] + bf[c];
    __syncthreads();
    g_penult[(n0 + ks) * C_ + c] = 0.0f;   // reset for replay

    float a0 = 0.0f, a1 = 0.0f;
    int d0 = ks * 128;
#pragma unroll 16
    for (int d = 0; d < 128; d++) {
        float w = Wc[(d0 + d) * C_ + c];
        a0 = fmaf(sp[0][d0 + d], w, a0);
        a1 = fmaf(sp[1][d0 + d], w, a1);
    }

    if (ks) { part[0][c] = a0; part[1][c] = a1; }
    __syncthreads();
    if (ks != 0) return;

    float b = bc[c];
    a0 += b + part[0][c];
    a1 += b + part[1][c];

    out[N_ * (K_ + 1) + N_ + (n0 + 0) * C_ + c] = a0;   // f_logit row n0
    out[N_ * (K_ + 1) + N_ + (n0 + 1) * C_ + c] = a1;   // f_logit row n0+1

    float v0 = a0 * a0, v1 = a1 * a1;
#pragma unroll
    for (int o = 16; o; o >>= 1) {
        v0 += __shfl_xor_sync(0xffffffffu, v0, o);
        v1 += __shfl_xor_sync(0xffffffffu, v1, o);
    }
    if ((c & 31) == 0) { sred[0][c >> 5] = v0; sred[1][c >> 5] = v1; }
    __syncthreads();
    float ss0 = 0.0f, ss1 = 0.0f;
#pragma unroll
    for (int g = 0; g < 8; g++) { ss0 += sred[0][g]; ss1 += sred[1][g]; }
    __syncthreads();

    float inv0 = 1.0f / fmaxf(sqrtf(ss0), 1e-12f);
    float inv1 = 1.0f / fmaxf(sqrtf(ss1), 1e-12f);
    float e0 = ex2f_(dist[(n0 + 0) * C_ + c] * a0 * inv0 * LOG2E);
    float e1 = ex2f_(dist[(n0 + 1) * C_ + c] * a1 * inv1 * LOG2E);
#pragma unroll
    for (int o = 16; o; o >>= 1) {
        e0 += __shfl_xor_sync(0xffffffffu, e0, o);
        e1 += __shfl_xor_sync(0xffffffffu, e1, o);
    }
    if ((c & 31) == 0) { sred[0][c >> 5] = e0; sred[1][c >> 5] = e1; }
    __syncthreads();
    if (c == 0) {
        float s0 = 0.0f, s1 = 0.0f;
#pragma unroll
        for (int g = 0; g < 8; g++) { s0 += sred[0][g]; s1 += sred[1][g]; }
        out[(n0 + 0) * (K_ + 1)] = lg2f_(s0) * (LN2 * INV_T);
        out[(n0 + 1) * (K_ + 1)] = lg2f_(s1) * (LN2 * INV_T);
    }
}

// ---------------------------------------------------------------------------
// lneg v7: J=2, ~80 regs (q staged via smem, only b2[16] persistent).
// grid 256 (32-wide k tiles), block 256, 2 CTAs/SM, smem 80KB.
// ---------------------------------------------------------------------------
#define SMA   0
#define SMB   65536
#define SMTOT 81920

__device__ __forceinline__ void ld_a_x4(uint32_t addr, uint32_t* a) {
    asm volatile("ldmatrix.sync.aligned.m8n8.x4.shared.b16 {%0,%1,%2,%3}, [%4];"
                 : "=r"(a[0]), "=r"(a[1]), "=r"(a[2]), "=r"(a[3]) : "r"(addr));
}

__global__ __launch_bounds__(256, 2)
void lneg_kernel(const float* __restrict__ q,
                 float* __restrict__ out) {
    extern __shared__ char smem[];
    uint32_t sb = su32(smem);
    int tid = threadIdx.x;
    int kx = tid & 31, cg = tid >> 5;
    int k0 = blockIdx.x * 32;

    // Pass 1: load q column-slice, accumulate ss, stash raw floats in A region
    float* ssp = (float*)(smem + SMA);            // 256 floats
    float* invp = (float*)(smem + SMA + 1024);    // 32 floats
    float* qstash = (float*)(smem + SMA + 2048);  // 8192 floats (32 KB)
    {
        const float* qp = q + (size_t)(cg * 32) * K_ + k0 + kx;
        float ss = 0.0f;
#pragma unroll
        for (int i = 0; i < 32; i++) {
            float v = qp[(size_t)i * K_];
            qstash[i * 256 + tid] = v;
            ss = fmaf(v, v, ss);
        }
        ssp[cg * 32 + kx] = ss;
    }
    __syncthreads();
    if (tid < 32) {
        float s = 0.0f;
#pragma unroll
        for (int g = 0; g < 8; g++) s += ssp[g * 32 + tid];
        invp[tid] = 1.0f / fmaxf(sqrtf(s), 1e-12f);
    }
    __syncthreads();

    // Pass 2: read back, scale, keep only b2[16] (bf16x2) persistent
    __nv_bfloat162 b2[16];
    {
        float iv = invp[kx];
#pragma unroll
        for (int i = 0; i < 16; ++i)
            b2[i] = __floats2bfloat162_rn(qstash[(2 * i) * 256 + tid] * iv,
                                          qstash[(2 * i + 1) * 256 + tid] * iv);
    }

    int warp = tid >> 5, lane = tid & 31;
    int mrow = (warp >> 1) * 32;
    int ncol = (warp & 1) * 16;

    float acc[2][2][4];
#pragma unroll
    for (int mt = 0; mt < 2; mt++)
#pragma unroll
        for (int nt = 0; nt < 2; nt++)
#pragma unroll
            for (int i = 0; i < 4; i++) acc[mt][nt][i] = 0.0f;

    int a_row0 = mrow + (lane & 15);
    int a_chL  = lane >> 4;
    int t4 = lane >> 3;
    int b_row = ncol + ((t4 >> 1) << 3) + (lane & 7);
    int b_chL = t4 & 1;

    uint32_t aAddr0 = sb + SMA + (a_row0) * 512;
    uint32_t aAddr1 = sb + SMA + (a_row0 + 16) * 512;
    uint32_t bAddr  = sb + SMB + b_row * 512;
    int aSw0 = (a_row0) & 7, aSw1 = (a_row0 + 16) & 7, bSw = b_row & 7;

#pragma unroll
    for (int j = 0; j < NJ; ++j) {
        __syncthreads();   // pass-2 reads done (j=0) / prior A+B consumed
        // stage A_j [128 x 256] -> swizzled tile (overwrites qstash)
        const uint4* Asrc = (const uint4*)(g_A + (size_t)j * N_ * C_);
#pragma unroll
        for (int t = 0; t < 16; ++t) {
            int lin = t * 256 + tid;
            int m = lin >> 5;
            int ch = lin & 31;
            *(uint4*)(smem + SMA + m * 512 + ((ch ^ (m & 7)) << 4)) = Asrc[lin];
        }
        // build B_j into the single B slot: j=0 -> b, j=1 -> b*b
#pragma unroll
        for (int i = 0; i < 16; ++i) {
            int c2 = cg * 32 + i * 2;
            uint32_t off = (uint32_t)(kx * 512 + (((c2 >> 3) ^ (kx & 7)) << 4)
                                      + (c2 & 7) * 2);
            __nv_bfloat162 val = (j == 0) ? b2[i] : __hmul2(b2[i], b2[i]);
            *(uint32_t*)(smem + SMB + off) = *(uint32_t*)&val;
        }
        __syncthreads();

        uint32_t a_f[2][2][4], b_f[2][4];
        ld_a_x4(aAddr0 + ((a_chL ^ aSw0) << 4), a_f[0][0]);
        ld_a_x4(aAddr1 + ((a_chL ^ aSw1) << 4), a_f[0][1]);
        ld_a_x4(bAddr + ((b_chL ^ bSw) << 4), b_f[0]);

#pragma unroll
        for (int kt = 0; kt < 16; ++kt) {
            int cur = kt & 1, nxt = cur ^ 1;
            if (kt < 15) {
                int ch = (kt + 1) * 2;
                ld_a_x4(aAddr0 + (((ch + a_chL) ^ aSw0) << 4), a_f[nxt][0]);
                ld_a_x4(aAddr1 + (((ch + a_chL) ^ aSw1) << 4), a_f[nxt][1]);
                ld_a_x4(bAddr + (((ch + b_chL) ^ bSw) << 4), b_f[nxt]);
            }
#pragma unroll
            for (int mt = 0; mt < 2; ++mt)
#pragma unroll
                for (int nt = 0; nt < 2; ++nt)
                    asm volatile(
                        "mma.sync.aligned.m16n8k16.row.col.f32.bf16.bf16.f32 "
                        "{%0,%1,%2,%3}, {%4,%5,%6,%7}, {%8,%9}, {%0,%1,%2,%3};"
                        : "+f"(acc[mt][nt][0]), "+f"(acc[mt][nt][1]),
                          "+f"(acc[mt][nt][2]), "+f"(acc[mt][nt][3])
                        : "r"(a_f[cur][mt][0]), "r"(a_f[cur][mt][1]),
                          "r"(a_f[cur][mt][2]), "r"(a_f[cur][mt][3]),
                          "r"(b_f[cur][nt * 2]), "r"(b_f[cur][nt * 2 + 1]));
        }
    }

    const float sc = LN2 * INV_T;
#pragma unroll
    for (int mt = 0; mt < 2; ++mt) {
#pragma unroll
        for (int nt = 0; nt < 2; ++nt) {
            int r = mrow + mt * 16 + (lane >> 2);
            int col = k0 + ncol + nt * 8 + (lane & 3) * 2;
            int base = r * (K_ + 1) + 1 + col;
            out[base]     = lg2f_(256.0f + acc[mt][nt][0]) * sc;
            out[base + 1] = lg2f_(256.0f + acc[mt][nt][1]) * sc;
            int base2 = (r + 8) * (K_ + 1) + 1 + col;
            out[base2]     = lg2f_(256.0f + acc[mt][nt][2]) * sc;
            out[base2 + 1] = lg2f_(256.0f + acc[mt][nt][3]) * sc;
        }
    }
}

extern "C" void kernel_launch(void* const* d_in, const int* in_sizes, int n_in,
                              void* d_out, int out_size) {
    const float* img  = (const float*)d_in[0];
    const float* Wf   = (const float*)d_in[1];
    const float* bf   = (const float*)d_in[2];
    const float* Wc   = (const float*)d_in[3];
    const float* bc   = (const float*)d_in[4];
    const float* dist = (const float*)d_in[5];
    const float* q    = (const float*)d_in[6];
    float* out = (float*)d_out;

    static cudaStream_t s1 = nullptr;
    static cudaEvent_t ev0 = nullptr, ev1 = nullptr;
    if (s1 == nullptr) {
        cudaStreamCreateWithFlags(&s1, cudaStreamNonBlocking);
        cudaEventCreateWithFlags(&ev0, cudaEventDisableTiming);
        cudaEventCreateWithFlags(&ev1, cudaEventDisableTiming);
        cudaFuncSetAttribute(lneg_kernel,
                             cudaFuncAttributeMaxDynamicSharedMemorySize, SMTOT);
    }

    // main: prep -> lneg          (l_neg columns)
    // s1:   gemm1 -> head         (f_logit, l_pos)
    cudaEventRecord(ev0, 0);
    cudaStreamWaitEvent(s1, ev0, 0);
    gemm1_kernel<<<dim3(4, 64), 256, 0, s1>>>(img, Wf);
    head_kernel<<<N_ / 2, 512, 0, s1>>>(Wc, bc, bf, dist, out);
    cudaEventRecord(ev1, s1);
    prep_kernel<<<N_, C_>>>(dist, out);
    lneg_kernel<<<K_ / 32, 256, SMTOT>>>(q, out);
    cudaStreamWaitEvent(0, ev1, 0);
}